// round 13
// baseline (speedup 1.0000x reference)
#include <cuda_runtime.h>
#include <cuda_bf16.h>
#include <cstddef>

// ---------------------------------------------------------------------------
// DCT_61340722921773 — round 13
//
// Per contiguous 64-float patch (8x8 X): Y = C^T X C, basis as immediates.
//
// R12 ncu: DRAM 63 / L1 64 / issue 59.5 / occ 77 — mixed latency-bound.
// Shfl runs in the LSU pipe (hence L1%), and the 3-step butterfly is a
// serial 26-cyc-latency chain per thread.
//
// This round: 2 patches per thread (p and p+npatch/2 so warp-level address
// patterns are unchanged), butterflies interleaved step-by-step -> 8
// independent shfls per step (2x ILP), 4 front-batched LDG (2x load MLP).
// __ldcs/__stcs: single-touch streaming data.
// ---------------------------------------------------------------------------

#define CA 0.35355339059327373f   // sqrt(1/8)
#define C1 0.4903926402016152f
#define C2 0.46193976625564337f
#define C3 0.4157348061512726f
#define C4 0.35355339059327373f
#define C5 0.2777851165098011f
#define C6 0.1913417161825449f
#define C7 0.09754516100806412f

// Cmat[u][i] = s(u) * cos((2i+1)*u*pi/16)
__device__ constexpr float Cmat[8][8] = {
    {  CA,  CA,  CA,  CA,  CA,  CA,  CA,  CA },
    {  C1,  C3,  C5,  C7, -C7, -C5, -C3, -C1 },
    {  C2,  C6, -C6, -C2, -C2, -C6,  C6,  C2 },
    {  C3, -C7, -C1, -C5,  C5,  C1,  C7, -C3 },
    {  C4, -C4, -C4,  C4,  C4, -C4, -C4,  C4 },
    {  C5, -C1,  C7,  C3, -C3, -C7,  C1, -C5 },
    {  C6, -C2,  C2, -C6, -C6,  C2, -C2,  C6 },
    {  C7, -C5,  C3, -C1,  C1, -C3,  C5, -C7 },
};

// Dual 8x8 transpose among 8 lanes, A and B interleaved per butterfly step
// so each step issues 8 independent shfls (hides the ~26-cyc shfl latency).
__device__ __forceinline__ void transpose8_dual(float a[8], float b[8], int g)
{
#pragma unroll
    for (int d = 1; d < 8; d <<= 1) {
        const bool hi = (g & d) != 0;
#pragma unroll
        for (int s0 = 0; s0 < 8; ++s0) {
            if (s0 & d) continue;
            const int s1 = s0 | d;
            float sendA = hi ? a[s0] : a[s1];
            float sendB = hi ? b[s0] : b[s1];
            float recvA = __shfl_xor_sync(0xffffffffu, sendA, d);
            float recvB = __shfl_xor_sync(0xffffffffu, sendB, d);
            if (hi) { a[s0] = recvA; b[s0] = recvB; }
            else    { a[s1] = recvA; b[s1] = recvB; }
        }
    }
}

// 8-point DCT with even/odd parity folding:
// out[j] = E[j] + O[j], out[7-j] = E[j] - O[j]  (j = 0..3)
__device__ __forceinline__ void dct8(const float x[8], float out[8])
{
#pragma unroll
    for (int j = 0; j < 4; ++j) {
        float E = x[0] * Cmat[0][j];
        E = fmaf(x[2], Cmat[2][j], E);
        E = fmaf(x[4], Cmat[4][j], E);
        E = fmaf(x[6], Cmat[6][j], E);
        float O = x[1] * Cmat[1][j];
        O = fmaf(x[3], Cmat[3][j], O);
        O = fmaf(x[5], Cmat[5][j], O);
        O = fmaf(x[7], Cmat[7][j], O);
        out[j]     = E + O;
        out[7 - j] = E - O;
    }
}

constexpr int THREADS = 256;

__global__ void __launch_bounds__(THREADS)
dct13_kernel(const float4* __restrict__ in, float4* __restrict__ out,
             int half)            // half = npatch / 2
{
    const int tid = blockIdx.x * THREADS + threadIdx.x;
    const int g   = tid & 7;
    const int q   = tid >> 3;
    if (q >= half) return;        // exact grid; groups never split

    const size_t f0 = (size_t)q * 16 + g * 2;           // patch q
    const size_t f1 = (size_t)(q + half) * 16 + g * 2;  // patch q + half

    // Front-batched loads: 4 independent LDG.128 (streaming).
    float4 a0 = __ldcs(in + f0);
    float4 a1 = __ldcs(in + f0 + 1);
    float4 b0 = __ldcs(in + f1);
    float4 b1 = __ldcs(in + f1 + 1);

    float xA[8] = { a0.x, a0.y, a0.z, a0.w, a1.x, a1.y, a1.z, a1.w };
    float xB[8] = { b0.x, b0.y, b0.z, b0.w, b1.x, b1.y, b1.z, b1.w };

    // Stage 1 (rows), both patches.
    float tA[8], tB[8];
    dct8(xA, tA);
    dct8(xB, tB);

    transpose8_dual(tA, tB, g);

    // Stage 2 (columns), both patches.
    float yA[8], yB[8];
    dct8(tA, yA);
    dct8(tB, yB);

    transpose8_dual(yA, yB, g);

    __stcs(out + f0,     make_float4(yA[0], yA[1], yA[2], yA[3]));
    __stcs(out + f0 + 1, make_float4(yA[4], yA[5], yA[6], yA[7]));
    __stcs(out + f1,     make_float4(yB[0], yB[1], yB[2], yB[3]));
    __stcs(out + f1 + 1, make_float4(yB[4], yB[5], yB[6], yB[7]));
}

extern "C" void kernel_launch(void* const* d_in, const int* in_sizes, int n_in,
                              void* d_out, int out_size)
{
    // d_in[0]: inputs, float32, (8,3,1024,1024); d_in[1]: 64x64 DCT matrix
    // (unused — basis baked in as immediates, identical formula).
    const float4* in  = (const float4*)d_in[0];
    float4*       out = (float4*)d_out;

    int npatch  = in_sizes[0] / 64;                 // 393216
    int half    = npatch / 2;                       // 196608
    int nthread = half * 8;                         // 1572864
    int blocks  = (nthread + THREADS - 1) / THREADS;  // 6144 (exact)

    dct13_kernel<<<blocks, THREADS>>>(in, out, half);
}